// round 10
// baseline (speedup 1.0000x reference)
#include <cuda_runtime.h>
#include <math.h>

// ---------------------------------------------------------------------------
// BigReimplementationPathIntegrator: conv encoder -> h0, then 100-step GRU.
// Inputs (metadata order):
//  0 images[128,3,72,72]  1 actions[128,100,2]
//  2 cw1[64,3,5,5] 3 cb1[64] 4 cw2[64,64,3,3] 5 cb2[64] 6 cw3[64,64,3,3] 7 cb3[64]
//  8 fw1[1024,1024] 9 fb1[1024] 10 fw2[512,1024] 11 fb2[512] 12 fw3[512,512] 13 fb3[512]
//  14 w_ih[1536,2] 15 w_hh[1536,512] 16 b_ih[1536] 17 b_hh[1536]
// Output: out[128,100,512] then hT[128,512]  (6,619,136 floats)
// ---------------------------------------------------------------------------

#define NB 128
#define NT 100
#define HID 512
#define OUT_HT_OFF (128 * 100 * 512)

// scratch (device globals: no allocation allowed)
__device__ float g_x1[128 * 64 * 24 * 24];
__device__ float g_x2[128 * 64 * 9 * 9];
__device__ float g_x3[128 * 1024];
__device__ float g_f1[128 * 1024];
__device__ float g_f2[128 * 512];
// h double buffer, quad-transposed layout: buffer p, float index
//   p*65536 + (k>>2)*512 + b*4 + (k&3)   == float4 [kq][b]
__device__ float g_hbuf[2 * 128 * 512];
__device__ unsigned int g_bar;

__global__ void __launch_bounds__(32, 1) reset_kernel() {
    if (threadIdx.x == 0) g_bar = 0u;
}

// ---------------- conv1: [128,3,72,72] -> [128,64,24,24], k5 s3 p2, relu ----
__global__ void __launch_bounds__(576, 1)
conv1_kernel(const float* __restrict__ img,
             const float* __restrict__ w,
             const float* __restrict__ bias) {
    extern __shared__ float sm[];
    float* s_img = sm;               // 3*74*74 padded image
    float* s_w   = sm + 3 * 74 * 74; // 64*75 weights
    int b = blockIdx.x, tid = threadIdx.x;  // 576 threads (24x24 outputs)
    for (int i = tid; i < 3 * 74 * 74; i += 576) s_img[i] = 0.f;
    __syncthreads();
    for (int i = tid; i < 3 * 72 * 72; i += 576) {
        int ic = i / (72 * 72); int rem = i - ic * 72 * 72;
        int r = rem / 72, c = rem - r * 72;
        s_img[(ic * 74 + r + 2) * 74 + c + 2] = img[((b * 3 + ic) * 72 + r) * 72 + c];
    }
    for (int i = tid; i < 64 * 75; i += 576) s_w[i] = w[i];
    __syncthreads();
    int oy = tid / 24, ox = tid - oy * 24;
    int by = oy * 3, bx = ox * 3;
    for (int oc = 0; oc < 64; oc += 4) {
        float a0 = bias[oc], a1 = bias[oc + 1], a2 = bias[oc + 2], a3 = bias[oc + 3];
        const float* w0 = s_w + oc * 75;
        #pragma unroll
        for (int ic = 0; ic < 3; ic++) {
            #pragma unroll
            for (int ky = 0; ky < 5; ky++) {
                const float* ip = s_img + (ic * 74 + by + ky) * 74 + bx;
                const float* wp = w0 + ic * 25 + ky * 5;
                #pragma unroll
                for (int kx = 0; kx < 5; kx++) {
                    float v = ip[kx];
                    a0 += wp[kx] * v;
                    a1 += wp[75 + kx] * v;
                    a2 += wp[150 + kx] * v;
                    a3 += wp[225 + kx] * v;
                }
            }
        }
        int o = (b * 64 + oc) * 576 + tid;
        g_x1[o]        = fmaxf(a0, 0.f);
        g_x1[o + 576]  = fmaxf(a1, 0.f);
        g_x1[o + 1152] = fmaxf(a2, 0.f);
        g_x1[o + 1728] = fmaxf(a3, 0.f);
    }
}

// ---------------- conv2: [128,64,24,24] -> [128,64,9,9], k3 s3 p2, relu -----
__global__ void __launch_bounds__(256, 1)
conv2_kernel(const float* __restrict__ w,
             const float* __restrict__ bias) {
    extern __shared__ float sm[];
    float* s_in = sm;                // 16*27*27 = 11664 padded, per ic-chunk
    float* s_w  = sm + 11664;        // 64*145 (row-padded)
    int b = blockIdx.x, tid = threadIdx.x;  // 256 threads
    int oc = tid >> 2, spl = tid & 3;
    float acc[21];
    int off[21];
    #pragma unroll
    for (int si = 0; si < 21; si++) {
        int s = spl + si * 4;
        if (s < 81) { int oyy = s / 9, oxx = s - oyy * 9; off[si] = oyy * 81 + oxx * 3; }
        else off[si] = 0;
        acc[si] = 0.f;
    }
    for (int c = 0; c < 4; c++) {
        int ic0 = c * 16;
        __syncthreads();
        for (int i = tid; i < 16 * 27 * 27; i += 256) {
            int ic = i / 729; int rem = i - ic * 729;
            int iy = rem / 27, ix = rem - iy * 27;
            float v = 0.f;
            if (iy >= 2 && iy < 26 && ix >= 2 && ix < 26)
                v = g_x1[((b * 64 + ic0 + ic) * 24 + (iy - 2)) * 24 + (ix - 2)];
            s_in[i] = v;
        }
        for (int i = tid; i < 64 * 144; i += 256) {
            int o = i / 144, rem = i - o * 144;
            s_w[o * 145 + rem] = w[(o * 64 + ic0) * 9 + rem];
        }
        __syncthreads();
        const float* wrow = s_w + oc * 145;
        #pragma unroll 2
        for (int ic = 0; ic < 16; ic++) {
            const float* inb = s_in + ic * 729;
            #pragma unroll
            for (int kk = 0; kk < 9; kk++) {
                int ky = kk / 3, kx = kk - ky * 3;
                float wv = wrow[ic * 9 + kk];
                int d = ky * 27 + kx;
                #pragma unroll
                for (int si = 0; si < 21; si++)
                    acc[si] += wv * inb[off[si] + d];
            }
        }
    }
    float bb = bias[oc];
    #pragma unroll
    for (int si = 0; si < 21; si++) {
        int s = spl + si * 4;
        if (s < 81) g_x2[(b * 64 + oc) * 81 + s] = fmaxf(acc[si] + bb, 0.f);
    }
}

// ---------------- conv3: [128,64,9,9] -> [128,64,4,4], k3 s3 p2, relu, flat -
__global__ void __launch_bounds__(256, 1)
conv3_kernel(const float* __restrict__ w,
             const float* __restrict__ bias) {
    extern __shared__ float sm[];
    float* s_in = sm;             // 64*144 (padded 12x12)
    float* s_w  = sm + 9216;      // 64*577 (row-padded)
    int b = blockIdx.x, tid = threadIdx.x;  // 256 threads
    for (int i = tid; i < 64 * 144; i += 256) {
        int ic = i / 144, rem = i - ic * 144;
        int iy = rem / 12, ix = rem - iy * 12;
        float v = 0.f;
        if (iy >= 2 && iy < 11 && ix >= 2 && ix < 11)
            v = g_x2[(b * 64 + ic) * 81 + (iy - 2) * 9 + (ix - 2)];
        s_in[i] = v;
    }
    for (int i = tid; i < 64 * 576; i += 256) {
        int o = i / 576, rem = i - o * 576;
        s_w[o * 577 + rem] = w[i];
    }
    __syncthreads();
    int sp = tid & 15, ocl = tid >> 4;     // sp = oy*4+ox, ocl 0..15 (4 oc each)
    int oyy = sp >> 2, oxx = sp & 3;
    int base = (oyy * 3) * 12 + oxx * 3;
    float acc[4];
    #pragma unroll
    for (int i = 0; i < 4; i++) acc[i] = bias[ocl + 16 * i];
    #pragma unroll 4
    for (int ic = 0; ic < 64; ic++) {
        const float* inb = s_in + ic * 144 + base;
        #pragma unroll
        for (int kk = 0; kk < 9; kk++) {
            int ky = kk / 3, kx = kk - ky * 3;
            float v = inb[ky * 12 + kx];
            #pragma unroll
            for (int i = 0; i < 4; i++)
                acc[i] += s_w[(ocl + 16 * i) * 577 + ic * 9 + kk] * v;
        }
    }
    #pragma unroll
    for (int i = 0; i < 4; i++) {
        int oc = ocl + 16 * i;
        g_x3[b * 1024 + oc * 16 + sp] = fmaxf(acc[i], 0.f);
    }
}

// ---------------- fc: C[128,N] = act(A[128,K] @ W[N,K]^T + bias) ------------
// mode 0: normal row-major store; mode 1: quad-transposed store into g_hbuf[0]
__global__ void __launch_bounds__(256, 1)
fc_kernel(const float* __restrict__ A, const float* __restrict__ W,
          const float* __restrict__ bias, float* __restrict__ C,
          int K, int N, int doRelu, int mode) {
    __shared__ float sA[32][33];
    __shared__ float sW[32][33];
    int tx = threadIdx.x, ty = threadIdx.y;       // 16 x 16
    int n0 = blockIdx.x * 32, m0 = blockIdx.y * 32;
    int tid = ty * 16 + tx;
    float c00 = 0.f, c01 = 0.f, c10 = 0.f, c11 = 0.f;
    for (int k0 = 0; k0 < K; k0 += 32) {
        for (int i = tid; i < 1024; i += 256) {
            int r = i >> 5, cc = i & 31;
            sA[r][cc] = A[(m0 + r) * K + k0 + cc];
            sW[r][cc] = W[(n0 + r) * K + k0 + cc];
        }
        __syncthreads();
        #pragma unroll
        for (int kk = 0; kk < 32; kk++) {
            float a0 = sA[ty * 2][kk],   a1 = sA[ty * 2 + 1][kk];
            float b0 = sW[tx * 2][kk],   b1 = sW[tx * 2 + 1][kk];
            c00 += a0 * b0; c01 += a0 * b1; c10 += a1 * b0; c11 += a1 * b1;
        }
        __syncthreads();
    }
    int m = m0 + ty * 2, n = n0 + tx * 2;
    float vv[4] = {c00, c01, c10, c11};
    #pragma unroll
    for (int q = 0; q < 4; q++) {
        int mm = m + (q >> 1), nn = n + (q & 1);
        float v = vv[q] + bias[nn];
        if (doRelu) v = fmaxf(v, 0.f);
        if (mode == 0) C[mm * N + nn] = v;
        else           C[(nn >> 2) * 512 + mm * 4 + (nn & 3)] = v;
    }
}

// ---------------- GRU: persistent, 128 CTAs, packed f32x2 FMA ---------------
__device__ __forceinline__ unsigned long long ffma2(unsigned long long a,
                                                    unsigned long long b,
                                                    unsigned long long c) {
    unsigned long long d;
    asm("fma.rn.f32x2 %0, %1, %2, %3;" : "=l"(d) : "l"(a), "l"(b), "l"(c));
    return d;
}
__device__ __forceinline__ float redu2(unsigned long long v) {
    float lo, hi;
    asm("mov.b64 {%0, %1}, %2;" : "=f"(lo), "=f"(hi) : "l"(v));
    return lo + hi;
}

#define WPAD 129   // float4 row pitch for w smem

__global__ void __launch_bounds__(256, 1)
gru_kernel(const float* __restrict__ actions,
           const float* __restrict__ w_ih,
           const float* __restrict__ w_hh,
           const float* __restrict__ b_ih,
           const float* __restrict__ b_hh,
           float* __restrict__ out) {
    extern __shared__ char smraw[];
    ulonglong2* s_h = (ulonglong2*)smraw;              // [kq=128][lb=32] float4
    ulonglong2* s_w = s_h + 128 * 32;                  // [row=48][WPAD] float4
    float* s_act = (float*)(s_w + 48 * WPAD);          // [lb=32][t=100][2]

    int tid = threadIdx.x;
    int lane = tid & 31, wi = tid >> 5;                // 8 warps: i-pair per warp
    int bb = blockIdx.x >> 5, ib = blockIdx.x & 31;    // 4 b-blocks x 32 i-blocks
    int b0 = bb * 32, i0 = ib * 16;
    int b = b0 + lane;

    // load w_hh slice: rows j = g*512 + i0 + il, for g in 0..2, il in 0..15
    for (int i = tid; i < 48 * 128; i += 256) {
        int row = i >> 7, kq = i & 127;                // row = g*16 + il
        int j = (row >> 4) * 512 + i0 + (row & 15);
        s_w[row * WPAD + kq] =
            *reinterpret_cast<const ulonglong2*>(w_hh + j * 512 + kq * 4);
    }
    // preload actions for this b-block
    for (int i = tid; i < 32 * 200; i += 256) s_act[i] = actions[b0 * 200 + i];

    // per-thread gate params (same across lanes -> broadcast LDG)
    float wi0[3][2], wi1[3][2], bihv[3][2], bhhv[3][2];
    #pragma unroll
    for (int g = 0; g < 3; g++)
        #pragma unroll
        for (int ii = 0; ii < 2; ii++) {
            int j = g * 512 + i0 + wi * 2 + ii;
            wi0[g][ii]  = w_ih[j * 2 + 0];
            wi1[g][ii]  = w_ih[j * 2 + 1];
            bihv[g][ii] = b_ih[j];
            bhhv[g][ii] = b_hh[j];
        }
    __syncthreads();

    for (int t = 0; t < NT; t++) {
        int rp = t & 1, wp = rp ^ 1;
        if (t > 0) {
            if (tid == 0) {
                unsigned target = 128u * (unsigned)t;
                while (*(volatile unsigned*)&g_bar < target) { }
                __threadfence();
            }
            __syncthreads();
        }
        // load h tile (quad-transposed global -> [kq][lb] smem), L2-level loads
        const float4* src4 = (const float4*)(g_hbuf + rp * 65536);
        for (int i = tid; i < 4096; i += 256) {
            int kq = i >> 5, lb = i & 31;
            float4 v = __ldcg(src4 + kq * 128 + b0 + lb);
            ((float4*)s_h)[kq * 32 + lb] = v;
        }
        __syncthreads();

        // gh dot products: 3 gates x 2 i per thread, packed f32x2 FMA
        ulonglong2 acc[3][2];
        #pragma unroll
        for (int g = 0; g < 3; g++)
            #pragma unroll
            for (int ii = 0; ii < 2; ii++) { acc[g][ii].x = 0ull; acc[g][ii].y = 0ull; }

        const ulonglong2* wb = s_w + (wi * 2) * WPAD;
        #pragma unroll 4
        for (int kq = 0; kq < 128; kq++) {
            ulonglong2 h = s_h[kq * 32 + lane];
            #pragma unroll
            for (int g = 0; g < 3; g++)
                #pragma unroll
                for (int ii = 0; ii < 2; ii++) {
                    ulonglong2 w = wb[(g * 16 + ii) * WPAD + kq];
                    acc[g][ii].x = ffma2(h.x, w.x, acc[g][ii].x);
                    acc[g][ii].y = ffma2(h.y, w.y, acc[g][ii].y);
                }
        }

        float a0 = s_act[lane * 200 + t * 2];
        float a1 = s_act[lane * 200 + t * 2 + 1];
        float* dst = g_hbuf + wp * 65536;
        #pragma unroll
        for (int ii = 0; ii < 2; ii++) {
            float ghr = redu2(acc[0][ii].x) + redu2(acc[0][ii].y) + bhhv[0][ii];
            float ghz = redu2(acc[1][ii].x) + redu2(acc[1][ii].y) + bhhv[1][ii];
            float ghn = redu2(acc[2][ii].x) + redu2(acc[2][ii].y) + bhhv[2][ii];
            float gir = fmaf(a1, wi1[0][ii], fmaf(a0, wi0[0][ii], bihv[0][ii]));
            float giz = fmaf(a1, wi1[1][ii], fmaf(a0, wi0[1][ii], bihv[1][ii]));
            float gin = fmaf(a1, wi1[2][ii], fmaf(a0, wi0[2][ii], bihv[2][ii]));
            float r = 1.f / (1.f + expf(-(gir + ghr)));
            float z = 1.f / (1.f + expf(-(giz + ghz)));
            float n = tanhf(gin + r * ghn);
            int ig = i0 + wi * 2 + ii;
            float hcur = ((const float*)s_h)[(ig >> 2) * 128 + lane * 4 + (ig & 3)];
            float hy = n + z * (hcur - n);
            out[(b * NT + t) * HID + ig] = hy;
            __stcg(dst + (ig >> 2) * 512 + b * 4 + (ig & 3), hy);
            if (t == NT - 1) out[OUT_HT_OFF + b * HID + ig] = hy;
        }
        // release: every thread fences its own h stores, then one arrive
        __threadfence();
        __syncthreads();
        if (tid == 0) atomicAdd(&g_bar, 1u);
    }
}

// ---------------------------------------------------------------------------
extern "C" void kernel_launch(void* const* d_in, const int* in_sizes, int n_in,
                              void* d_out, int out_size) {
    const float* images  = (const float*)d_in[0];
    const float* actions = (const float*)d_in[1];
    const float* cw1 = (const float*)d_in[2];
    const float* cb1 = (const float*)d_in[3];
    const float* cw2 = (const float*)d_in[4];
    const float* cb2 = (const float*)d_in[5];
    const float* cw3 = (const float*)d_in[6];
    const float* cb3 = (const float*)d_in[7];
    const float* fw1 = (const float*)d_in[8];
    const float* fb1 = (const float*)d_in[9];
    const float* fw2 = (const float*)d_in[10];
    const float* fb2 = (const float*)d_in[11];
    const float* fw3 = (const float*)d_in[12];
    const float* fb3 = (const float*)d_in[13];
    const float* w_ih = (const float*)d_in[14];
    const float* w_hh = (const float*)d_in[15];
    const float* b_ih = (const float*)d_in[16];
    const float* b_hh = (const float*)d_in[17];
    float* out = (float*)d_out;

    float *p_x3, *p_f1, *p_f2, *p_hb;
    cudaGetSymbolAddress((void**)&p_x3, g_x3);
    cudaGetSymbolAddress((void**)&p_f1, g_f1);
    cudaGetSymbolAddress((void**)&p_f2, g_f2);
    cudaGetSymbolAddress((void**)&p_hb, g_hbuf);

    const int SM1 = (3 * 74 * 74 + 64 * 75) * 4;           // 84912
    const int SM2 = (11664 + 64 * 145) * 4;                // 83776
    const int SM3 = (9216 + 64 * 577) * 4;                 // 184576
    const int SMG = 128 * 32 * 16 + 48 * WPAD * 16 + 32 * 200 * 4;  // 190208

    cudaFuncSetAttribute(conv1_kernel, cudaFuncAttributeMaxDynamicSharedMemorySize, SM1);
    cudaFuncSetAttribute(conv2_kernel, cudaFuncAttributeMaxDynamicSharedMemorySize, SM2);
    cudaFuncSetAttribute(conv3_kernel, cudaFuncAttributeMaxDynamicSharedMemorySize, SM3);
    cudaFuncSetAttribute(gru_kernel,   cudaFuncAttributeMaxDynamicSharedMemorySize, SMG);

    reset_kernel<<<1, 32>>>();
    conv1_kernel<<<128, 576, SM1>>>(images, cw1, cb1);
    conv2_kernel<<<128, 256, SM2>>>(cw2, cb2);
    conv3_kernel<<<128, 256, SM3>>>(cw3, cb3);
    fc_kernel<<<dim3(32, 4), dim3(16, 16)>>>(p_x3, fw1, fb1, p_f1, 1024, 1024, 1, 0);
    fc_kernel<<<dim3(16, 4), dim3(16, 16)>>>(p_f1, fw2, fb2, p_f2, 1024, 512, 1, 0);
    // fc3: no relu, write h0 quad-transposed into g_hbuf buffer 0
    fc_kernel<<<dim3(16, 4), dim3(16, 16)>>>(p_f2, fw3, fb3, p_hb, 512, 512, 0, 1);
    gru_kernel<<<128, 256, SMG>>>(actions, w_ih, w_hh, b_ih, b_hh, out);
}

// round 11
// speedup vs baseline: 1.0459x; 1.0459x over previous
#include <cuda_runtime.h>
#include <math.h>

// ---------------------------------------------------------------------------
// BigReimplementationPathIntegrator: conv encoder -> h0, then 100-step GRU.
// Inputs (metadata order):
//  0 images[128,3,72,72]  1 actions[128,100,2]
//  2 cw1[64,3,5,5] 3 cb1[64] 4 cw2[64,64,3,3] 5 cb2[64] 6 cw3[64,64,3,3] 7 cb3[64]
//  8 fw1[1024,1024] 9 fb1[1024] 10 fw2[512,1024] 11 fb2[512] 12 fw3[512,512] 13 fb3[512]
//  14 w_ih[1536,2] 15 w_hh[1536,512] 16 b_ih[1536] 17 b_hh[1536]
// Output: out[128,100,512] then hT[128,512]  (6,619,136 floats)
// ---------------------------------------------------------------------------

#define NB 128
#define NT 100
#define HID 512
#define OUT_HT_OFF (128 * 100 * 512)

// scratch (device globals: no allocation allowed)
__device__ float g_x1[128 * 64 * 24 * 24];
__device__ float g_x2[128 * 64 * 9 * 9];
__device__ float g_x3[128 * 1024];
__device__ float g_f1[128 * 1024];
__device__ float g_f2[128 * 512];
// h double buffer, quad-transposed layout: buffer p, float index
//   p*65536 + (k>>2)*512 + b*4 + (k&3)   == float4 [kq][b]
__device__ float g_hbuf[2 * 128 * 512];
// per-CTA step flags, 128B apart (32 u32 stride) to avoid line sharing
__device__ unsigned int g_flags[128 * 32];

__global__ void __launch_bounds__(128, 1) reset_kernel() {
    g_flags[threadIdx.x * 32] = 0u;
}

// ---------------- conv1: [128,3,72,72] -> [128,64,24,24], k5 s3 p2, relu ----
__global__ void __launch_bounds__(576, 1)
conv1_kernel(const float* __restrict__ img,
             const float* __restrict__ w,
             const float* __restrict__ bias) {
    extern __shared__ float sm[];
    float* s_img = sm;               // 3*74*74 padded image
    float* s_w   = sm + 3 * 74 * 74; // 64*75 weights
    int b = blockIdx.x, tid = threadIdx.x;  // 576 threads (24x24 outputs)
    for (int i = tid; i < 3 * 74 * 74; i += 576) s_img[i] = 0.f;
    __syncthreads();
    for (int i = tid; i < 3 * 72 * 72; i += 576) {
        int ic = i / (72 * 72); int rem = i - ic * 72 * 72;
        int r = rem / 72, c = rem - r * 72;
        s_img[(ic * 74 + r + 2) * 74 + c + 2] = img[((b * 3 + ic) * 72 + r) * 72 + c];
    }
    for (int i = tid; i < 64 * 75; i += 576) s_w[i] = w[i];
    __syncthreads();
    int oy = tid / 24, ox = tid - oy * 24;
    int by = oy * 3, bx = ox * 3;
    for (int oc = 0; oc < 64; oc += 4) {
        float a0 = bias[oc], a1 = bias[oc + 1], a2 = bias[oc + 2], a3 = bias[oc + 3];
        const float* w0 = s_w + oc * 75;
        #pragma unroll
        for (int ic = 0; ic < 3; ic++) {
            #pragma unroll
            for (int ky = 0; ky < 5; ky++) {
                const float* ip = s_img + (ic * 74 + by + ky) * 74 + bx;
                const float* wp = w0 + ic * 25 + ky * 5;
                #pragma unroll
                for (int kx = 0; kx < 5; kx++) {
                    float v = ip[kx];
                    a0 += wp[kx] * v;
                    a1 += wp[75 + kx] * v;
                    a2 += wp[150 + kx] * v;
                    a3 += wp[225 + kx] * v;
                }
            }
        }
        int o = (b * 64 + oc) * 576 + tid;
        g_x1[o]        = fmaxf(a0, 0.f);
        g_x1[o + 576]  = fmaxf(a1, 0.f);
        g_x1[o + 1152] = fmaxf(a2, 0.f);
        g_x1[o + 1728] = fmaxf(a3, 0.f);
    }
}

// ---------------- conv2: [128,64,24,24] -> [128,64,9,9], k3 s3 p2, relu -----
__global__ void __launch_bounds__(256, 1)
conv2_kernel(const float* __restrict__ w,
             const float* __restrict__ bias) {
    extern __shared__ float sm[];
    float* s_in = sm;                // 16*27*27 = 11664 padded, per ic-chunk
    float* s_w  = sm + 11664;        // 64*145 (row-padded)
    int b = blockIdx.x, tid = threadIdx.x;  // 256 threads
    int oc = tid >> 2, spl = tid & 3;
    float acc[21];
    int off[21];
    #pragma unroll
    for (int si = 0; si < 21; si++) {
        int s = spl + si * 4;
        if (s < 81) { int oyy = s / 9, oxx = s - oyy * 9; off[si] = oyy * 81 + oxx * 3; }
        else off[si] = 0;
        acc[si] = 0.f;
    }
    for (int c = 0; c < 4; c++) {
        int ic0 = c * 16;
        __syncthreads();
        for (int i = tid; i < 16 * 27 * 27; i += 256) {
            int ic = i / 729; int rem = i - ic * 729;
            int iy = rem / 27, ix = rem - iy * 27;
            float v = 0.f;
            if (iy >= 2 && iy < 26 && ix >= 2 && ix < 26)
                v = g_x1[((b * 64 + ic0 + ic) * 24 + (iy - 2)) * 24 + (ix - 2)];
            s_in[i] = v;
        }
        for (int i = tid; i < 64 * 144; i += 256) {
            int o = i / 144, rem = i - o * 144;
            s_w[o * 145 + rem] = w[(o * 64 + ic0) * 9 + rem];
        }
        __syncthreads();
        const float* wrow = s_w + oc * 145;
        #pragma unroll 2
        for (int ic = 0; ic < 16; ic++) {
            const float* inb = s_in + ic * 729;
            #pragma unroll
            for (int kk = 0; kk < 9; kk++) {
                int ky = kk / 3, kx = kk - ky * 3;
                float wv = wrow[ic * 9 + kk];
                int d = ky * 27 + kx;
                #pragma unroll
                for (int si = 0; si < 21; si++)
                    acc[si] += wv * inb[off[si] + d];
            }
        }
    }
    float bb = bias[oc];
    #pragma unroll
    for (int si = 0; si < 21; si++) {
        int s = spl + si * 4;
        if (s < 81) g_x2[(b * 64 + oc) * 81 + s] = fmaxf(acc[si] + bb, 0.f);
    }
}

// ---------------- conv3: [128,64,9,9] -> [128,64,4,4], k3 s3 p2, relu, flat -
__global__ void __launch_bounds__(256, 1)
conv3_kernel(const float* __restrict__ w,
             const float* __restrict__ bias) {
    extern __shared__ float sm[];
    float* s_in = sm;             // 64*144 (padded 12x12)
    float* s_w  = sm + 9216;      // 64*577 (row-padded)
    int b = blockIdx.x, tid = threadIdx.x;  // 256 threads
    for (int i = tid; i < 64 * 144; i += 256) {
        int ic = i / 144, rem = i - ic * 144;
        int iy = rem / 12, ix = rem - iy * 12;
        float v = 0.f;
        if (iy >= 2 && iy < 11 && ix >= 2 && ix < 11)
            v = g_x2[(b * 64 + ic) * 81 + (iy - 2) * 9 + (ix - 2)];
        s_in[i] = v;
    }
    for (int i = tid; i < 64 * 576; i += 256) {
        int o = i / 576, rem = i - o * 576;
        s_w[o * 577 + rem] = w[i];
    }
    __syncthreads();
    int sp = tid & 15, ocl = tid >> 4;     // sp = oy*4+ox, ocl 0..15 (4 oc each)
    int oyy = sp >> 2, oxx = sp & 3;
    int base = (oyy * 3) * 12 + oxx * 3;
    float acc[4];
    #pragma unroll
    for (int i = 0; i < 4; i++) acc[i] = bias[ocl + 16 * i];
    #pragma unroll 4
    for (int ic = 0; ic < 64; ic++) {
        const float* inb = s_in + ic * 144 + base;
        #pragma unroll
        for (int kk = 0; kk < 9; kk++) {
            int ky = kk / 3, kx = kk - ky * 3;
            float v = inb[ky * 12 + kx];
            #pragma unroll
            for (int i = 0; i < 4; i++)
                acc[i] += s_w[(ocl + 16 * i) * 577 + ic * 9 + kk] * v;
        }
    }
    #pragma unroll
    for (int i = 0; i < 4; i++) {
        int oc = ocl + 16 * i;
        g_x3[b * 1024 + oc * 16 + sp] = fmaxf(acc[i], 0.f);
    }
}

// ---------------- fc: C[128,N] = act(A[128,K] @ W[N,K]^T + bias) ------------
// mode 0: normal row-major store; mode 1: quad-transposed store into g_hbuf[0]
__global__ void __launch_bounds__(256, 1)
fc_kernel(const float* __restrict__ A, const float* __restrict__ W,
          const float* __restrict__ bias, float* __restrict__ C,
          int K, int N, int doRelu, int mode) {
    __shared__ float sA[32][33];
    __shared__ float sW[32][33];
    int tx = threadIdx.x, ty = threadIdx.y;       // 16 x 16
    int n0 = blockIdx.x * 32, m0 = blockIdx.y * 32;
    int tid = ty * 16 + tx;
    float c00 = 0.f, c01 = 0.f, c10 = 0.f, c11 = 0.f;
    for (int k0 = 0; k0 < K; k0 += 32) {
        for (int i = tid; i < 1024; i += 256) {
            int r = i >> 5, cc = i & 31;
            sA[r][cc] = A[(m0 + r) * K + k0 + cc];
            sW[r][cc] = W[(n0 + r) * K + k0 + cc];
        }
        __syncthreads();
        #pragma unroll
        for (int kk = 0; kk < 32; kk++) {
            float a0 = sA[ty * 2][kk],   a1 = sA[ty * 2 + 1][kk];
            float b0 = sW[tx * 2][kk],   b1 = sW[tx * 2 + 1][kk];
            c00 += a0 * b0; c01 += a0 * b1; c10 += a1 * b0; c11 += a1 * b1;
        }
        __syncthreads();
    }
    int m = m0 + ty * 2, n = n0 + tx * 2;
    float vv[4] = {c00, c01, c10, c11};
    #pragma unroll
    for (int q = 0; q < 4; q++) {
        int mm = m + (q >> 1), nn = n + (q & 1);
        float v = vv[q] + bias[nn];
        if (doRelu) v = fmaxf(v, 0.f);
        if (mode == 0) C[mm * N + nn] = v;
        else           C[(nn >> 2) * 512 + mm * 4 + (nn & 3)] = v;
    }
}

// ---------------- GRU: persistent, 128 CTAs, packed f32x2 FMA ---------------
__device__ __forceinline__ unsigned long long ffma2(unsigned long long a,
                                                    unsigned long long b,
                                                    unsigned long long c) {
    unsigned long long d;
    asm("fma.rn.f32x2 %0, %1, %2, %3;" : "=l"(d) : "l"(a), "l"(b), "l"(c));
    return d;
}
__device__ __forceinline__ float redu2(unsigned long long v) {
    float lo, hi;
    asm("mov.b64 {%0, %1}, %2;" : "=f"(lo), "=f"(hi) : "l"(v));
    return lo + hi;
}
__device__ __forceinline__ unsigned ld_acquire(const unsigned* p) {
    unsigned v;
    asm volatile("ld.acquire.gpu.u32 %0, [%1];" : "=r"(v) : "l"(p) : "memory");
    return v;
}
__device__ __forceinline__ void st_release(unsigned* p, unsigned v) {
    asm volatile("st.release.gpu.u32 [%0], %1;" :: "l"(p), "r"(v) : "memory");
}

#define WPAD 129   // float4 row pitch for w smem

__global__ void __launch_bounds__(256, 1)
gru_kernel(const float* __restrict__ actions,
           const float* __restrict__ w_ih,
           const float* __restrict__ w_hh,
           const float* __restrict__ b_ih,
           const float* __restrict__ b_hh,
           float* __restrict__ out) {
    extern __shared__ char smraw[];
    ulonglong2* s_h = (ulonglong2*)smraw;              // [kq=128][lb=32] float4
    ulonglong2* s_w = s_h + 128 * 32;                  // [row=48][WPAD] float4

    int tid = threadIdx.x;
    int lane = tid & 31, wi = tid >> 5;                // 8 warps: i-pair per warp
    int bb = blockIdx.x >> 5, ib = blockIdx.x & 31;    // 4 b-blocks x 32 i-blocks
    int b0 = bb * 32, i0 = ib * 16;
    int b = b0 + lane;

    // load w_hh slice: rows j = g*512 + i0 + il, for g in 0..2, il in 0..15
    for (int i = tid; i < 48 * 128; i += 256) {
        int row = i >> 7, kq = i & 127;                // row = g*16 + il
        int j = (row >> 4) * 512 + i0 + (row & 15);
        s_w[row * WPAD + kq] =
            *reinterpret_cast<const ulonglong2*>(w_hh + j * 512 + kq * 4);
    }

    // per-thread gate params (same across lanes -> broadcast LDG)
    float wi0[3][2], wi1[3][2], bihv[3][2], bhhv[3][2];
    #pragma unroll
    for (int g = 0; g < 3; g++)
        #pragma unroll
        for (int ii = 0; ii < 2; ii++) {
            int j = g * 512 + i0 + wi * 2 + ii;
            wi0[g][ii]  = w_ih[j * 2 + 0];
            wi1[g][ii]  = w_ih[j * 2 + 1];
            bihv[g][ii] = b_ih[j];
            bhhv[g][ii] = b_hh[j];
        }
    __syncthreads();

    // hoisted w row pointers for this thread's 6 (g,ii) rows
    const ulonglong2* wp00 = s_w + (0 * 16 + wi * 2 + 0) * WPAD;
    const ulonglong2* wp01 = s_w + (0 * 16 + wi * 2 + 1) * WPAD;
    const ulonglong2* wp10 = s_w + (1 * 16 + wi * 2 + 0) * WPAD;
    const ulonglong2* wp11 = s_w + (1 * 16 + wi * 2 + 1) * WPAD;
    const ulonglong2* wp20 = s_w + (2 * 16 + wi * 2 + 0) * WPAD;
    const ulonglong2* wp21 = s_w + (2 * 16 + wi * 2 + 1) * WPAD;

    int ig0 = i0 + wi * 2;                 // first of the 2 output dims
    unsigned* myflag = g_flags + blockIdx.x * 32;

    for (int t = 0; t < NT; t++) {
        int rp = t & 1, wp = rp ^ 1;
        // early, independent loads for this step (off the barrier path)
        float a0 = __ldg(actions + b * 200 + t * 2);
        float a1 = __ldg(actions + b * 200 + t * 2 + 1);

        if (t > 0) {
            // wait for the 32 producer CTAs of this b-block (one flag per lane)
            if (tid < 32) {
                const unsigned* fp = g_flags + (bb * 32 + tid) * 32;
                while (ld_acquire(fp) < (unsigned)t) { }
            }
            __syncthreads();
        }
        // load h tile (quad-transposed global -> [kq][lb] smem), L2-level loads
        const float4* src4 = (const float4*)(g_hbuf + rp * 65536);
        #pragma unroll
        for (int i = 0; i < 16; i++) {
            int idx = tid + i * 256;
            int kq = idx >> 5, lb = idx & 31;
            float4 v = __ldcg(src4 + kq * 128 + b0 + lb);
            ((float4*)s_h)[kq * 32 + lb] = v;
        }
        __syncthreads();

        // gh dot products: 3 gates x 2 i per thread, packed f32x2 FMA
        ulonglong2 a00 = {0ull, 0ull}, a01 = {0ull, 0ull};
        ulonglong2 a10 = {0ull, 0ull}, a11 = {0ull, 0ull};
        ulonglong2 a20 = {0ull, 0ull}, a21 = {0ull, 0ull};
        #pragma unroll 16
        for (int kq = 0; kq < 128; kq++) {
            ulonglong2 h = s_h[kq * 32 + lane];
            ulonglong2 w;
            w = wp00[kq]; a00.x = ffma2(h.x, w.x, a00.x); a00.y = ffma2(h.y, w.y, a00.y);
            w = wp01[kq]; a01.x = ffma2(h.x, w.x, a01.x); a01.y = ffma2(h.y, w.y, a01.y);
            w = wp10[kq]; a10.x = ffma2(h.x, w.x, a10.x); a10.y = ffma2(h.y, w.y, a10.y);
            w = wp11[kq]; a11.x = ffma2(h.x, w.x, a11.x); a11.y = ffma2(h.y, w.y, a11.y);
            w = wp20[kq]; a20.x = ffma2(h.x, w.x, a20.x); a20.y = ffma2(h.y, w.y, a20.y);
            w = wp21[kq]; a21.x = ffma2(h.x, w.x, a21.x); a21.y = ffma2(h.y, w.y, a21.y);
        }

        float hy0, hy1;
        {
            float ghr = redu2(a00.x) + redu2(a00.y) + bhhv[0][0];
            float ghz = redu2(a10.x) + redu2(a10.y) + bhhv[1][0];
            float ghn = redu2(a20.x) + redu2(a20.y) + bhhv[2][0];
            float gir = fmaf(a1, wi1[0][0], fmaf(a0, wi0[0][0], bihv[0][0]));
            float giz = fmaf(a1, wi1[1][0], fmaf(a0, wi0[1][0], bihv[1][0]));
            float gin = fmaf(a1, wi1[2][0], fmaf(a0, wi0[2][0], bihv[2][0]));
            float r = 1.f / (1.f + expf(-(gir + ghr)));
            float z = 1.f / (1.f + expf(-(giz + ghz)));
            float n = tanhf(gin + r * ghn);
            float hc = ((const float*)s_h)[(ig0 >> 2) * 128 + lane * 4 + (ig0 & 3)];
            hy0 = n + z * (hc - n);
        }
        {
            int ig = ig0 + 1;
            float ghr = redu2(a01.x) + redu2(a01.y) + bhhv[0][1];
            float ghz = redu2(a11.x) + redu2(a11.y) + bhhv[1][1];
            float ghn = redu2(a21.x) + redu2(a21.y) + bhhv[2][1];
            float gir = fmaf(a1, wi1[0][1], fmaf(a0, wi0[0][1], bihv[0][1]));
            float giz = fmaf(a1, wi1[1][1], fmaf(a0, wi0[1][1], bihv[1][1]));
            float gin = fmaf(a1, wi1[2][1], fmaf(a0, wi0[2][1], bihv[2][1]));
            float r = 1.f / (1.f + expf(-(gir + ghr)));
            float z = 1.f / (1.f + expf(-(giz + ghz)));
            float n = tanhf(gin + r * ghn);
            float hc = ((const float*)s_h)[(ig >> 2) * 128 + lane * 4 + (ig & 3)];
            hy1 = n + z * (hc - n);
        }

        // critical path: h double-buffer store + release flag
        float* dst = g_hbuf + wp * 65536;
        __stcg(dst + (ig0 >> 2) * 512 + b * 4 + (ig0 & 3), hy0);
        __stcg(dst + ((ig0 + 1) >> 2) * 512 + b * 4 + ((ig0 + 1) & 3), hy1);
        __threadfence();
        __syncthreads();                     // all stores of this CTA fenced
        if (tid == 0) st_release(myflag, (unsigned)(t + 1));

        // off critical path: sequence output (+ final hT)
        out[(b * NT + t) * HID + ig0]     = hy0;
        out[(b * NT + t) * HID + ig0 + 1] = hy1;
        if (t == NT - 1) {
            out[OUT_HT_OFF + b * HID + ig0]     = hy0;
            out[OUT_HT_OFF + b * HID + ig0 + 1] = hy1;
        }
    }
}

// ---------------------------------------------------------------------------
extern "C" void kernel_launch(void* const* d_in, const int* in_sizes, int n_in,
                              void* d_out, int out_size) {
    const float* images  = (const float*)d_in[0];
    const float* actions = (const float*)d_in[1];
    const float* cw1 = (const float*)d_in[2];
    const float* cb1 = (const float*)d_in[3];
    const float* cw2 = (const float*)d_in[4];
    const float* cb2 = (const float*)d_in[5];
    const float* cw3 = (const float*)d_in[6];
    const float* cb3 = (const float*)d_in[7];
    const float* fw1 = (const float*)d_in[8];
    const float* fb1 = (const float*)d_in[9];
    const float* fw2 = (const float*)d_in[10];
    const float* fb2 = (const float*)d_in[11];
    const float* fw3 = (const float*)d_in[12];
    const float* fb3 = (const float*)d_in[13];
    const float* w_ih = (const float*)d_in[14];
    const float* w_hh = (const float*)d_in[15];
    const float* b_ih = (const float*)d_in[16];
    const float* b_hh = (const float*)d_in[17];
    float* out = (float*)d_out;

    float *p_x3, *p_f1, *p_f2, *p_hb;
    cudaGetSymbolAddress((void**)&p_x3, g_x3);
    cudaGetSymbolAddress((void**)&p_f1, g_f1);
    cudaGetSymbolAddress((void**)&p_f2, g_f2);
    cudaGetSymbolAddress((void**)&p_hb, g_hbuf);

    const int SM1 = (3 * 74 * 74 + 64 * 75) * 4;           // 84912
    const int SM2 = (11664 + 64 * 145) * 4;                // 83776
    const int SM3 = (9216 + 64 * 577) * 4;                 // 184576
    const int SMG = 128 * 32 * 16 + 48 * WPAD * 16;        // 164608

    cudaFuncSetAttribute(conv1_kernel, cudaFuncAttributeMaxDynamicSharedMemorySize, SM1);
    cudaFuncSetAttribute(conv2_kernel, cudaFuncAttributeMaxDynamicSharedMemorySize, SM2);
    cudaFuncSetAttribute(conv3_kernel, cudaFuncAttributeMaxDynamicSharedMemorySize, SM3);
    cudaFuncSetAttribute(gru_kernel,   cudaFuncAttributeMaxDynamicSharedMemorySize, SMG);

    reset_kernel<<<1, 128>>>();
    conv1_kernel<<<128, 576, SM1>>>(images, cw1, cb1);
    conv2_kernel<<<128, 256, SM2>>>(cw2, cb2);
    conv3_kernel<<<128, 256, SM3>>>(cw3, cb3);
    fc_kernel<<<dim3(32, 4), dim3(16, 16)>>>(p_x3, fw1, fb1, p_f1, 1024, 1024, 1, 0);
    fc_kernel<<<dim3(16, 4), dim3(16, 16)>>>(p_f1, fw2, fb2, p_f2, 1024, 512, 1, 0);
    // fc3: no relu, write h0 quad-transposed into g_hbuf buffer 0
    fc_kernel<<<dim3(16, 4), dim3(16, 16)>>>(p_f2, fw3, fb3, p_hb, 512, 512, 0, 1);
    gru_kernel<<<128, 256, SMG>>>(actions, w_ih, w_hh, b_ih, b_hh, out);
}